// round 8
// baseline (speedup 1.0000x reference)
#include <cuda_runtime.h>
#include <cstdint>

#define HDIM 128
#define NMAX 100032
#define EMAX 1600000
#define GMAX 1024
#define NCLS 10
#define BN_EPS 1e-5
#define SLOPE 0.01f
#define SCAN_CHUNK 2048
#define MAXBLK 64
#define KP 20                 // padded smem k-stride (bank = 4g+t4, conflict-free)

// ---------------- device scratch (static, no allocation) ----------------
__device__ __align__(16) float  g_agg[(size_t)NMAX * HDIM];
__device__ __align__(16) float  g_t  [(size_t)NMAX * HDIM];
__device__ __align__(16) float  g_h  [(size_t)NMAX * HDIM];
__device__ __align__(16) float  g_hg [GMAX * HDIM];
__device__ __align__(16) float  g_cnt[GMAX];
__device__ __align__(16) double g_stats[2 * HDIM];
__device__ __align__(16) float  g_coef [2 * HDIM];
__device__ __align__(16) float  g_wth[4][HDIM * HDIM];   // W^T hi (tf32), [n][k]
__device__ __align__(16) float  g_wtl[4][HDIM * HDIM];   // W^T lo (tf32), [n][k]
__device__ int g_deg   [NMAX];
__device__ int g_rowptr[NMAX + 1];
__device__ int g_cur   [NMAX];
__device__ int g_eidx  [EMAX];
__device__ int g_bsum  [MAXBLK];
__device__ int g_boff  [MAXBLK];

__device__ __forceinline__ float lrelu(float x) { return x > 0.f ? x : SLOPE * x; }

__device__ __forceinline__ uint32_t f2tf32(float v) {
    uint32_t u;
    asm("cvt.rna.tf32.f32 %0, %1;" : "=r"(u) : "f"(v));
    return u;
}

__device__ __forceinline__ void mma_tf32(float* d,
                                         uint32_t a0, uint32_t a1, uint32_t a2, uint32_t a3,
                                         uint32_t b0, uint32_t b1) {
    asm volatile("mma.sync.aligned.m16n8k8.row.col.f32.tf32.tf32.f32 "
                 "{%0,%1,%2,%3}, {%4,%5,%6,%7}, {%8,%9}, {%0,%1,%2,%3};"
                 : "+f"(d[0]), "+f"(d[1]), "+f"(d[2]), "+f"(d[3])
                 : "r"(a0), "r"(a1), "r"(a2), "r"(a3), "r"(b0), "r"(b1));
}

// ---------------- zero small scratch + CSR counters ----------------
__global__ void zero_kernel(int N) {
    int idx    = blockIdx.x * blockDim.x + threadIdx.x;
    int stride = gridDim.x * blockDim.x;
    float4 z = make_float4(0.f, 0.f, 0.f, 0.f);
    float4* h4 = reinterpret_cast<float4*>(g_hg);
    for (int i = idx; i < (GMAX * HDIM) >> 2; i += stride) h4[i] = z;
    for (int i = idx; i < N; i += stride) { g_deg[i] = 0; g_cur[i] = 0; }
    if (idx < GMAX) g_cnt[idx] = 0.f;
    if (idx < 2 * HDIM) g_stats[idx] = 0.0;
}

__global__ void zstats_kernel() {
    int idx = threadIdx.x;
    if (idx < 2 * HDIM) g_stats[idx] = 0.0;
}

// ---------------- weight prep: transpose + 3xTF32 split ----------------
__global__ void wprep_kernel(const float* __restrict__ W0, const float* __restrict__ W1,
                             const float* __restrict__ W2, const float* __restrict__ W3) {
    int idx = blockIdx.x * blockDim.x + threadIdx.x;   // 0 .. 4*16384-1
    int m   = idx >> 14;
    int rem = idx & 16383;
    int n   = rem >> 7;
    int k   = rem & 127;
    const float* W = (m == 0) ? W0 : (m == 1) ? W1 : (m == 2) ? W2 : W3;
    float v  = W[k * HDIM + n];
    float hf = __uint_as_float(f2tf32(v));
    float lf = __uint_as_float(f2tf32(v - hf));
    g_wth[m][rem] = hf;
    g_wtl[m][rem] = lf;
}

// ---------------- node counts per graph ----------------
__global__ void count_kernel(const int* __restrict__ batch, int N) {
    int i = blockIdx.x * blockDim.x + threadIdx.x;
    if (i < N) atomicAdd(&g_cnt[batch[i]], 1.0f);
}

// ---------------- CSR build ----------------
__global__ void hist_kernel(const int* __restrict__ dst, int E) {
    int e = blockIdx.x * blockDim.x + threadIdx.x;
    if (e < E) atomicAdd(&g_deg[dst[e]], 1);
}

__global__ void scan1_kernel(int N) {
    __shared__ int ts[256];
    int b = blockIdx.x;
    int t = threadIdx.x;
    int base = b * SCAN_CHUNK + t * 8;
    int v[8];
    int s = 0;
#pragma unroll
    for (int i = 0; i < 8; i++) {
        int idx = base + i;
        v[i] = (idx < N) ? g_deg[idx] : 0;
        s += v[i];
    }
    ts[t] = s;
    __syncthreads();
#pragma unroll
    for (int off = 1; off < 256; off <<= 1) {
        int x = (t >= off) ? ts[t - off] : 0;
        __syncthreads();
        ts[t] += x;
        __syncthreads();
    }
    int run = ts[t] - s;
#pragma unroll
    for (int i = 0; i < 8; i++) {
        int idx = base + i;
        if (idx < N) g_rowptr[idx] = run;
        run += v[i];
    }
    if (t == 255) g_bsum[b] = ts[255];
}

__global__ void scan2_kernel(int nb) {
    __shared__ int ts[MAXBLK];
    int t = threadIdx.x;
    int v = (t < nb) ? g_bsum[t] : 0;
    ts[t] = v;
    __syncthreads();
#pragma unroll
    for (int off = 1; off < MAXBLK; off <<= 1) {
        int x = (t >= off) ? ts[t - off] : 0;
        __syncthreads();
        ts[t] += x;
        __syncthreads();
    }
    g_boff[t] = ts[t] - v;
}

__global__ void scan3_kernel(int N, int nb) {
    int i = blockIdx.x * blockDim.x + threadIdx.x;
    if (i < N) g_rowptr[i] += g_boff[i / SCAN_CHUNK];
    if (i == N) g_rowptr[N] = g_boff[nb - 1] + g_bsum[nb - 1];
}

__global__ void fill_kernel(const int* __restrict__ src,
                            const int* __restrict__ dst, int E) {
    int e = blockIdx.x * blockDim.x + threadIdx.x;
    if (e < E) {
        int d = dst[e];
        int pos = atomicAdd(&g_cur[d], 1);
        g_eidx[g_rowptr[d] + pos] = src[e];
    }
}

// ---------------- gather aggregation: agg[i] = BN?( x[i] + sum_{j->i} x[j] ) ----------------
template<int APPLY_BN>
__global__ void aggregate_kernel(const float* __restrict__ Xext, int N) {
    int i = (blockIdx.x * blockDim.x + threadIdx.x) >> 5;
    if (i >= N) return;
    int lane = threadIdx.x & 31;
    const float* X = APPLY_BN ? g_h : Xext;
    int base = g_rowptr[i];
    int end  = g_rowptr[i + 1];

    float4 acc = *reinterpret_cast<const float4*>(X + (size_t)i * HDIM + lane * 4);
    int e = base;
    for (; e + 4 <= end; e += 4) {
        int s0 = g_eidx[e], s1 = g_eidx[e + 1], s2 = g_eidx[e + 2], s3 = g_eidx[e + 3];
        float4 v0 = *reinterpret_cast<const float4*>(X + (size_t)s0 * HDIM + lane * 4);
        float4 v1 = *reinterpret_cast<const float4*>(X + (size_t)s1 * HDIM + lane * 4);
        float4 v2 = *reinterpret_cast<const float4*>(X + (size_t)s2 * HDIM + lane * 4);
        float4 v3 = *reinterpret_cast<const float4*>(X + (size_t)s3 * HDIM + lane * 4);
        acc.x += v0.x + v1.x + v2.x + v3.x;
        acc.y += v0.y + v1.y + v2.y + v3.y;
        acc.z += v0.z + v1.z + v2.z + v3.z;
        acc.w += v0.w + v1.w + v2.w + v3.w;
    }
    for (; e < end; e++) {
        int s = g_eidx[e];
        float4 v = *reinterpret_cast<const float4*>(X + (size_t)s * HDIM + lane * 4);
        acc.x += v.x; acc.y += v.y; acc.z += v.z; acc.w += v.w;
    }
    if (APPLY_BN) {
        float cnt = (float)(end - base + 1);
        float4 a = *reinterpret_cast<const float4*>(&g_coef[lane * 4]);
        float4 c = *reinterpret_cast<const float4*>(&g_coef[HDIM + lane * 4]);
        acc.x = fmaf(a.x, acc.x, cnt * c.x);
        acc.y = fmaf(a.y, acc.y, cnt * c.y);
        acc.z = fmaf(a.z, acc.z, cnt * c.z);
        acc.w = fmaf(a.w, acc.w, cnt * c.w);
    }
    *reinterpret_cast<float4*>(g_agg + (size_t)i * HDIM + lane * 4) = acc;
}

// ---------------- TF32 tensor-core GEMM: [N,128] @ [128,128] + bias, leaky ----------------
// 3xTF32 split for ~fp32 accuracy. Block: 256 thr, tile 128x128, K chunks of 16.
// Warps: warp_m = wid&3 (32 rows), warp_n = wid>>2 (64 cols). Per-warp: 2 m-tiles x 8 n-tiles.
// MODE 0: A = g_agg -> g_t. MODE 1: A = g_t -> g_h (or pooled raw sums if POOL) + BN stats.
template<int MODE, int POOL>
__global__ void __launch_bounds__(256, 2)
gemm_mma(const float* __restrict__ WtH,
         const float* __restrict__ WtL,
         const float* __restrict__ bias,
         const int* __restrict__ batch,
         int N) {
    __shared__ __align__(16) float AsH[HDIM * KP];
    __shared__ __align__(16) float AsL[HDIM * KP];
    __shared__ __align__(16) float BsH[HDIM * KP];
    __shared__ __align__(16) float BsL[HDIM * KP];
    __shared__ float biasS[HDIM];
    __shared__ float csum[HDIM];
    __shared__ float csq [HDIM];

    const int tid  = threadIdx.x;
    const int wid  = tid >> 5;
    const int lane = tid & 31;
    const int g    = lane >> 2;
    const int t4   = lane & 3;
    const int mb   = (wid & 3) * 32;
    const int nb   = (wid >> 2) * 64;
    const int row0 = blockIdx.x * 128;

    const float* X = (MODE == 0) ? g_agg : g_t;

    if (tid < HDIM) {
        biasS[tid] = bias[tid];
        if (MODE == 1) { csum[tid] = 0.f; csq[tid] = 0.f; }
    }

    float acc[2][8][4];
#pragma unroll
    for (int i = 0; i < 2; i++)
#pragma unroll
        for (int j = 0; j < 8; j++)
#pragma unroll
            for (int q = 0; q < 4; q++) acc[i][j][q] = 0.f;

    const int sr = tid >> 1;          // staging row 0..127
    const int sk = (tid & 1) * 8;     // staging k offset 0 or 8

    for (int ci = 0; ci < 8; ci++) {
        __syncthreads();
        // ---- stage A (split hi/lo on the fly) ----
        {
            float v[8];
            int grow = row0 + sr;
            if (grow < N) {
                float4 v0 = *reinterpret_cast<const float4*>(X + (size_t)grow * HDIM + ci * 16 + sk);
                float4 v1 = *reinterpret_cast<const float4*>(X + (size_t)grow * HDIM + ci * 16 + sk + 4);
                v[0] = v0.x; v[1] = v0.y; v[2] = v0.z; v[3] = v0.w;
                v[4] = v1.x; v[5] = v1.y; v[6] = v1.z; v[7] = v1.w;
            } else {
#pragma unroll
                for (int q = 0; q < 8; q++) v[q] = 0.f;
            }
            float h[8], l[8];
#pragma unroll
            for (int q = 0; q < 8; q++) {
                h[q] = __uint_as_float(f2tf32(v[q]));
                l[q] = __uint_as_float(f2tf32(v[q] - h[q]));
            }
            float* pH = &AsH[sr * KP + sk];
            float* pL = &AsL[sr * KP + sk];
            *reinterpret_cast<float4*>(pH)     = make_float4(h[0], h[1], h[2], h[3]);
            *reinterpret_cast<float4*>(pH + 4) = make_float4(h[4], h[5], h[6], h[7]);
            *reinterpret_cast<float4*>(pL)     = make_float4(l[0], l[1], l[2], l[3]);
            *reinterpret_cast<float4*>(pL + 4) = make_float4(l[4], l[5], l[6], l[7]);
        }
        // ---- stage B (pre-split weights, plain copy) ----
        {
            const float* srcH = WtH + sr * HDIM + ci * 16 + sk;
            const float* srcL = WtL + sr * HDIM + ci * 16 + sk;
            float4 h0 = *reinterpret_cast<const float4*>(srcH);
            float4 h1 = *reinterpret_cast<const float4*>(srcH + 4);
            float4 l0 = *reinterpret_cast<const float4*>(srcL);
            float4 l1 = *reinterpret_cast<const float4*>(srcL + 4);
            float* pH = &BsH[sr * KP + sk];
            float* pL = &BsL[sr * KP + sk];
            *reinterpret_cast<float4*>(pH)     = h0;
            *reinterpret_cast<float4*>(pH + 4) = h1;
            *reinterpret_cast<float4*>(pL)     = l0;
            *reinterpret_cast<float4*>(pL + 4) = l1;
        }
        __syncthreads();

        // ---- compute: 2 k-steps of 8 ----
#pragma unroll
        for (int ks = 0; ks < 2; ks++) {
            const int k8 = ks * 8 + t4;
            uint32_t aH[2][4], aL2[2][4];
#pragma unroll
            for (int i = 0; i < 2; i++) {
                int base = (mb + i * 16 + g) * KP + k8;
                aH[i][0]  = __float_as_uint(AsH[base]);
                aH[i][1]  = __float_as_uint(AsH[base + 8 * KP]);
                aH[i][2]  = __float_as_uint(AsH[base + 4]);
                aH[i][3]  = __float_as_uint(AsH[base + 8 * KP + 4]);
                aL2[i][0] = __float_as_uint(AsL[base]);
                aL2[i][1] = __float_as_uint(AsL[base + 8 * KP]);
                aL2[i][2] = __float_as_uint(AsL[base + 4]);
                aL2[i][3] = __float_as_uint(AsL[base + 8 * KP + 4]);
            }
#pragma unroll
            for (int j = 0; j < 8; j++) {
                int bbase = (nb + j * 8 + g) * KP + k8;
                uint32_t bH0 = __float_as_uint(BsH[bbase]);
                uint32_t bH1 = __float_as_uint(BsH[bbase + 4]);
                uint32_t bL0 = __float_as_uint(BsL[bbase]);
                uint32_t bL1 = __float_as_uint(BsL[bbase + 4]);
#pragma unroll
                for (int i = 0; i < 2; i++) {
                    mma_tf32(acc[i][j], aL2[i][0], aL2[i][1], aL2[i][2], aL2[i][3], bH0, bH1);
                    mma_tf32(acc[i][j], aH[i][0],  aH[i][1],  aH[i][2],  aH[i][3],  bL0, bL1);
                    mma_tf32(acc[i][j], aH[i][0],  aH[i][1],  aH[i][2],  aH[i][3],  bH0, bH1);
                }
            }
        }
    }

    // ---- epilogue ----
    // thread owns rows: row0 + mb + rr*8 + g (rr=0..3; i = rr>>1, dpair = (rr&1)*2)
    // cols: nb + j*8 + 2*t4 (+1)
    if (MODE == 0) {
#pragma unroll
        for (int rr = 0; rr < 4; rr++) {
            int r = row0 + mb + rr * 8 + g;
            if (r < N) {
                int i = rr >> 1, h = (rr & 1) * 2;
#pragma unroll
                for (int j = 0; j < 8; j++) {
                    int c0 = nb + j * 8 + 2 * t4;
                    float2 o;
                    o.x = lrelu(acc[i][j][h]     + biasS[c0]);
                    o.y = lrelu(acc[i][j][h + 1] + biasS[c0 + 1]);
                    *reinterpret_cast<float2*>(g_t + (size_t)r * HDIM + c0) = o;
                }
            }
        }
    } else {
        float s0[16], s1[16];
#pragma unroll
        for (int q = 0; q < 16; q++) { s0[q] = 0.f; s1[q] = 0.f; }
        float p[16];
        int curg = -1;
#pragma unroll
        for (int rr = 0; rr < 4; rr++) {
            int r = row0 + mb + rr * 8 + g;
            if (r < N) {
                int i = rr >> 1, h = (rr & 1) * 2;
                float o[16];
#pragma unroll
                for (int j = 0; j < 8; j++) {
                    int c0 = nb + j * 8 + 2 * t4;
                    o[2 * j]     = lrelu(acc[i][j][h]     + biasS[c0]);
                    o[2 * j + 1] = lrelu(acc[i][j][h + 1] + biasS[c0 + 1]);
                }
#pragma unroll
                for (int q = 0; q < 16; q++) { s0[q] += o[q]; s1[q] += o[q] * o[q]; }
                if (!POOL) {
                    float* dst = g_h + (size_t)r * HDIM;
#pragma unroll
                    for (int j = 0; j < 8; j++) {
                        int c0 = nb + j * 8 + 2 * t4;
                        *reinterpret_cast<float2*>(dst + c0) = make_float2(o[2 * j], o[2 * j + 1]);
                    }
                } else {
                    int gb = batch[r];
                    if (gb != curg) {
                        if (curg >= 0) {
#pragma unroll
                            for (int j = 0; j < 8; j++) {
                                int c0 = nb + j * 8 + 2 * t4;
                                float* dp = g_hg + (size_t)curg * HDIM + c0;
                                asm volatile("red.global.add.v2.f32 [%0], {%1, %2};"
                                             :: "l"(dp), "f"(p[2 * j]), "f"(p[2 * j + 1]) : "memory");
                            }
                        }
                        curg = gb;
#pragma unroll
                        for (int q = 0; q < 16; q++) p[q] = o[q];
                    } else {
#pragma unroll
                        for (int q = 0; q < 16; q++) p[q] += o[q];
                    }
                }
            }
        }
        if (POOL && curg >= 0) {
#pragma unroll
            for (int j = 0; j < 8; j++) {
                int c0 = nb + j * 8 + 2 * t4;
                float* dp = g_hg + (size_t)curg * HDIM + c0;
                asm volatile("red.global.add.v2.f32 [%0], {%1, %2};"
                             :: "l"(dp), "f"(p[2 * j]), "f"(p[2 * j + 1]) : "memory");
            }
        }
        // BN statistics via smem then global double atomics
#pragma unroll
        for (int q = 0; q < 16; q++) {
            int col = nb + (q >> 1) * 8 + 2 * t4 + (q & 1);
            atomicAdd(&csum[col], s0[q]);
            atomicAdd(&csq [col], s1[q]);
        }
        __syncthreads();
        if (tid < HDIM) {
            atomicAdd(&g_stats[tid],        (double)csum[tid]);
            atomicAdd(&g_stats[HDIM + tid], (double)csq[tid]);
        }
    }
}

// ---------------- BN coefficients ----------------
__global__ void coef_kernel(const float* __restrict__ gamma,
                            const float* __restrict__ beta, int N) {
    int c = threadIdx.x;
    double mean = g_stats[c] / (double)N;
    double var  = g_stats[HDIM + c] / (double)N - mean * mean;
    float a = (float)((double)gamma[c] / sqrt(var + (double)BN_EPS));
    g_coef[c]        = a;
    g_coef[HDIM + c] = beta[c] - a * (float)mean;
}

// ---------------- head ----------------
__global__ void head_kernel(const float* __restrict__ fcW1, const float* __restrict__ fcb1,
                            const float* __restrict__ fcW2, const float* __restrict__ fcb2,
                            float* __restrict__ out) {
    __shared__ float s[HDIM];
    __shared__ float y[HDIM];
    __shared__ float z[NCLS];
    __shared__ float red2[2];
    int g = blockIdx.x;
    int j = threadIdx.x;

    float cnt = g_cnt[g];
    s[j] = g_coef[j] * g_hg[g * HDIM + j] + g_coef[HDIM + j] * cnt;
    __syncthreads();

    float acc = fcb1[j];
#pragma unroll 8
    for (int k = 0; k < HDIM; k++) acc += s[k] * fcW1[k * HDIM + j];
    y[j] = lrelu(acc);
    __syncthreads();

    if (j < NCLS) {
        float acc2 = fcb2[j];
#pragma unroll 8
        for (int k = 0; k < HDIM; k++) acc2 += y[k] * fcW2[k * NCLS + j];
        z[j] = acc2;
    }
    __syncthreads();

    if (j == 0) {
        float m = z[0];
#pragma unroll
        for (int c = 1; c < NCLS; c++) m = fmaxf(m, z[c]);
        float se = 0.f;
#pragma unroll
        for (int c = 0; c < NCLS; c++) se += expf(z[c] - m);
        red2[0] = m;
        red2[1] = logf(se);
    }
    __syncthreads();
    if (j < NCLS) out[g * NCLS + j] = z[j] - red2[0] - red2[1];
}

// ---------------- launch ----------------
extern "C" void kernel_launch(void* const* d_in, const int* in_sizes, int n_in,
                              void* d_out, int out_size) {
    const float* x    = (const float*)d_in[0];
    const float* W1a  = (const float*)d_in[1];
    const float* b1a  = (const float*)d_in[2];
    const float* W1b  = (const float*)d_in[3];
    const float* b1b  = (const float*)d_in[4];
    const float* g1   = (const float*)d_in[5];
    const float* be1  = (const float*)d_in[6];
    const float* W2a  = (const float*)d_in[7];
    const float* b2a  = (const float*)d_in[8];
    const float* W2b  = (const float*)d_in[9];
    const float* b2b  = (const float*)d_in[10];
    const float* g2   = (const float*)d_in[11];
    const float* be2  = (const float*)d_in[12];
    const float* fcW1 = (const float*)d_in[13];
    const float* fcb1 = (const float*)d_in[14];
    const float* fcW2 = (const float*)d_in[15];
    const float* fcb2 = (const float*)d_in[16];
    const int* ei     = (const int*)d_in[17];   // int32 (JAX x64 disabled)
    const int* batch  = (const int*)d_in[18];   // int32
    float* out = (float*)d_out;

    const int N = in_sizes[0] / HDIM;
    const int E = in_sizes[17] / 2;
    const int* esrc = ei;
    const int* edst = ei + E;

    float* wth; float* wtl;
    cudaGetSymbolAddress((void**)&wth, g_wth);
    cudaGetSymbolAddress((void**)&wtl, g_wtl);

    const int mmaBlocks  = (N + 127) / 128;
    const int aggBlocks  = (N + 7) / 8;
    const int eBlocks    = (E + 255) / 256;
    const int scanBlocks = (N + SCAN_CHUNK - 1) / SCAN_CHUNK;

    // ---- CSR build + weight prep ----
    zero_kernel<<<512, 256>>>(N);
    wprep_kernel<<<256, 256>>>(W1a, W1b, W2a, W2b);
    count_kernel<<<(N + 255) / 256, 256>>>(batch, N);
    hist_kernel<<<eBlocks, 256>>>(edst, E);
    scan1_kernel<<<scanBlocks, 256>>>(N);
    scan2_kernel<<<1, MAXBLK>>>(scanBlocks);
    scan3_kernel<<<(N + 256) / 256, 256>>>(N, scanBlocks);
    fill_kernel<<<eBlocks, 256>>>(esrc, edst, E);

    // ---- layer 1 ----
    aggregate_kernel<0><<<aggBlocks, 256>>>(x, N);
    gemm_mma<0, 0><<<mmaBlocks, 256>>>(wth + 0 * HDIM * HDIM, wtl + 0 * HDIM * HDIM, b1a, nullptr, N);
    gemm_mma<1, 0><<<mmaBlocks, 256>>>(wth + 1 * HDIM * HDIM, wtl + 1 * HDIM * HDIM, b1b, nullptr, N);
    coef_kernel<<<1, HDIM>>>(g1, be1, N);

    // ---- layer 2 (BN1 folded into aggregation) ----
    zstats_kernel<<<1, 256>>>();
    aggregate_kernel<1><<<aggBlocks, 256>>>(nullptr, N);
    gemm_mma<0, 0><<<mmaBlocks, 256>>>(wth + 2 * HDIM * HDIM, wtl + 2 * HDIM * HDIM, b2a, nullptr, N);
    gemm_mma<1, 1><<<mmaBlocks, 256>>>(wth + 3 * HDIM * HDIM, wtl + 3 * HDIM * HDIM, b2b, batch, N);
    coef_kernel<<<1, HDIM>>>(g2, be2, N);

    // ---- head ----
    head_kernel<<<GMAX, HDIM>>>(fcW1, fcb1, fcW2, fcb2, out);
}

// round 9
// speedup vs baseline: 1.1178x; 1.1178x over previous
#include <cuda_runtime.h>
#include <cstdint>

#define HDIM 128
#define NMAX 100032
#define EMAX 1600000
#define GMAX 1024
#define NCLS 10
#define BN_EPS 1e-5
#define SLOPE 0.01f
#define SCAN_CHUNK 2048
#define MAXBLK 64

// ---------------- device scratch (static, no allocation) ----------------
__device__ __align__(16) float  g_agg[(size_t)NMAX * HDIM];
__device__ __align__(16) float  g_t  [(size_t)NMAX * HDIM];
__device__ __align__(16) float  g_h  [(size_t)NMAX * HDIM];
__device__ __align__(16) float  g_hg [GMAX * HDIM];
__device__ __align__(16) float  g_cnt[GMAX];
__device__ __align__(16) double g_stats[2 * HDIM];
__device__ __align__(16) float  g_coef [2 * HDIM];
__device__ int g_deg   [NMAX];
__device__ int g_rowptr[NMAX + 1];
__device__ int g_cur   [NMAX];
__device__ int g_eidx  [EMAX];
__device__ int g_bsum  [MAXBLK];
__device__ int g_boff  [MAXBLK];

__device__ __forceinline__ float lrelu(float x) { return x > 0.f ? x : SLOPE * x; }

// ---------------- zero small scratch + CSR counters ----------------
__global__ void zero_kernel(int N) {
    int idx    = blockIdx.x * blockDim.x + threadIdx.x;
    int stride = gridDim.x * blockDim.x;
    float4 z = make_float4(0.f, 0.f, 0.f, 0.f);
    float4* h4 = reinterpret_cast<float4*>(g_hg);
    for (int i = idx; i < (GMAX * HDIM) >> 2; i += stride) h4[i] = z;
    for (int i = idx; i < N; i += stride) { g_deg[i] = 0; g_cur[i] = 0; }
    if (idx < GMAX) g_cnt[idx] = 0.f;
    if (idx < 2 * HDIM) g_stats[idx] = 0.0;
}

// ---------------- combined edge histogram + per-graph node counts ----------------
__global__ void hist_kernel(const int* __restrict__ dst,
                            const int* __restrict__ batch, int E, int N) {
    int e = blockIdx.x * blockDim.x + threadIdx.x;
    if (e < E) atomicAdd(&g_deg[dst[e]], 1);
    if (e < N) atomicAdd(&g_cnt[batch[e]], 1.0f);
}

// ---------------- CSR build: 3-phase multi-block exclusive scan ----------------
__global__ void scan1_kernel(int N) {
    __shared__ int ts[256];
    int b = blockIdx.x;
    int t = threadIdx.x;
    int base = b * SCAN_CHUNK + t * 8;
    int v[8];
    int s = 0;
#pragma unroll
    for (int i = 0; i < 8; i++) {
        int idx = base + i;
        v[i] = (idx < N) ? g_deg[idx] : 0;
        s += v[i];
    }
    ts[t] = s;
    __syncthreads();
#pragma unroll
    for (int off = 1; off < 256; off <<= 1) {
        int x = (t >= off) ? ts[t - off] : 0;
        __syncthreads();
        ts[t] += x;
        __syncthreads();
    }
    int run = ts[t] - s;
#pragma unroll
    for (int i = 0; i < 8; i++) {
        int idx = base + i;
        if (idx < N) g_rowptr[idx] = run;
        run += v[i];
    }
    if (t == 255) g_bsum[b] = ts[255];
}

__global__ void scan2_kernel(int nb) {
    __shared__ int ts[MAXBLK];
    int t = threadIdx.x;
    int v = (t < nb) ? g_bsum[t] : 0;
    ts[t] = v;
    __syncthreads();
#pragma unroll
    for (int off = 1; off < MAXBLK; off <<= 1) {
        int x = (t >= off) ? ts[t - off] : 0;
        __syncthreads();
        ts[t] += x;
        __syncthreads();
    }
    g_boff[t] = ts[t] - v;
}

__global__ void scan3_kernel(int N, int nb) {
    int i = blockIdx.x * blockDim.x + threadIdx.x;
    if (i < N) g_rowptr[i] += g_boff[i / SCAN_CHUNK];
    if (i == N) g_rowptr[N] = g_boff[nb - 1] + g_bsum[nb - 1];
}

__global__ void fill_kernel(const int* __restrict__ src,
                            const int* __restrict__ dst, int E) {
    int e = blockIdx.x * blockDim.x + threadIdx.x;
    if (e < E) {
        int d = dst[e];
        int pos = atomicAdd(&g_cur[d], 1);
        g_eidx[g_rowptr[d] + pos] = src[e];
    }
}

// ---------------- gather aggregation: agg[i] = BN?( x[i] + sum_{j->i} x[j] ) ----------------
template<int APPLY_BN>
__global__ void aggregate_kernel(const float* __restrict__ Xext, int N) {
    int i = (blockIdx.x * blockDim.x + threadIdx.x) >> 5;
    if (i >= N) return;
    int lane = threadIdx.x & 31;
    const float* X = APPLY_BN ? g_h : Xext;
    int base = g_rowptr[i];
    int end  = g_rowptr[i + 1];

    float4 acc = *reinterpret_cast<const float4*>(X + (size_t)i * HDIM + lane * 4);
    int e = base;
    for (; e + 4 <= end; e += 4) {
        int s0 = g_eidx[e], s1 = g_eidx[e + 1], s2 = g_eidx[e + 2], s3 = g_eidx[e + 3];
        float4 v0 = *reinterpret_cast<const float4*>(X + (size_t)s0 * HDIM + lane * 4);
        float4 v1 = *reinterpret_cast<const float4*>(X + (size_t)s1 * HDIM + lane * 4);
        float4 v2 = *reinterpret_cast<const float4*>(X + (size_t)s2 * HDIM + lane * 4);
        float4 v3 = *reinterpret_cast<const float4*>(X + (size_t)s3 * HDIM + lane * 4);
        acc.x += v0.x + v1.x + v2.x + v3.x;
        acc.y += v0.y + v1.y + v2.y + v3.y;
        acc.z += v0.z + v1.z + v2.z + v3.z;
        acc.w += v0.w + v1.w + v2.w + v3.w;
    }
    for (; e < end; e++) {
        int s = g_eidx[e];
        float4 v = *reinterpret_cast<const float4*>(X + (size_t)s * HDIM + lane * 4);
        acc.x += v.x; acc.y += v.y; acc.z += v.z; acc.w += v.w;
    }
    if (APPLY_BN) {
        float cnt = (float)(end - base + 1);
        float4 a = *reinterpret_cast<const float4*>(&g_coef[lane * 4]);
        float4 c = *reinterpret_cast<const float4*>(&g_coef[HDIM + lane * 4]);
        acc.x = fmaf(a.x, acc.x, cnt * c.x);
        acc.y = fmaf(a.y, acc.y, cnt * c.y);
        acc.z = fmaf(a.z, acc.z, cnt * c.z);
        acc.w = fmaf(a.w, acc.w, cnt * c.w);
    }
    *reinterpret_cast<float4*>(g_agg + (size_t)i * HDIM + lane * 4) = acc;
}

// ---------------- fused GEMM: [N,128] @ [128,128] + bias, leaky ----------------
// 128 threads, 64x128 tile, BK=16, per-thread 8x8 (1.0 FMA per LDS byte).
// tcol = tid&15 -> cols tcol*8..+7 ; trow = tid>>4 -> rows trow*8..+7.
// MODE 0: A = g_agg -> g_t. MODE 1: A = g_t -> g_h (or pooled raw sums if POOL) + BN stats.
template<int MODE, int POOL>
__global__ void __launch_bounds__(128)
gemm_kernel(const float* __restrict__ W,
            const float* __restrict__ bias,
            const int* __restrict__ batch,
            int N) {
    __shared__ __align__(16) float As[16][72];
    __shared__ __align__(16) float Ws[16][HDIM];
    __shared__ float csum[HDIM];
    __shared__ float csq [HDIM];

    const int tid  = threadIdx.x;
    const int tcol = tid & 15;
    const int trow = tid >> 4;
    const int row0 = blockIdx.x * 64;

    const float* X = (MODE == 0) ? g_agg : g_t;

    float acc[8][8];
#pragma unroll
    for (int i = 0; i < 8; i++)
#pragma unroll
        for (int j = 0; j < 8; j++) acc[i][j] = 0.f;

    for (int k0 = 0; k0 < HDIM; k0 += 16) {
        // stage A: 64 rows x 16 k = 256 float4 slots, 2 per thread (transposed store)
#pragma unroll
        for (int it = 0; it < 2; it++) {
            int slot = tid + it * 128;
            int r    = slot >> 2;
            int kq   = (slot & 3) * 4;
            float4 av = make_float4(0.f, 0.f, 0.f, 0.f);
            int grow = row0 + r;
            if (grow < N)
                av = *reinterpret_cast<const float4*>(X + (size_t)grow * HDIM + k0 + kq);
            As[kq + 0][r] = av.x;
            As[kq + 1][r] = av.y;
            As[kq + 2][r] = av.z;
            As[kq + 3][r] = av.w;
        }
        // stage W: 16 rows x 128 = 512 float4, 4 per thread
        {
            const float4* wsrc = reinterpret_cast<const float4*>(W + k0 * HDIM);
            float4* wdst = reinterpret_cast<float4*>(&Ws[0][0]);
#pragma unroll
            for (int it = 0; it < 4; it++) wdst[tid + it * 128] = wsrc[tid + it * 128];
        }
        __syncthreads();

#pragma unroll
        for (int kk = 0; kk < 16; kk++) {
            float4 a0 = *reinterpret_cast<const float4*>(&As[kk][trow * 8]);
            float4 a1 = *reinterpret_cast<const float4*>(&As[kk][trow * 8 + 4]);
            float4 w0 = *reinterpret_cast<const float4*>(&Ws[kk][tcol * 8]);
            float4 w1 = *reinterpret_cast<const float4*>(&Ws[kk][tcol * 8 + 4]);
            float a[8] = {a0.x, a0.y, a0.z, a0.w, a1.x, a1.y, a1.z, a1.w};
            float w[8] = {w0.x, w0.y, w0.z, w0.w, w1.x, w1.y, w1.z, w1.w};
#pragma unroll
            for (int i = 0; i < 8; i++)
#pragma unroll
                for (int j = 0; j < 8; j++)
                    acc[i][j] = fmaf(a[i], w[j], acc[i][j]);
        }
        __syncthreads();
    }

    float4 b0 = *reinterpret_cast<const float4*>(bias + tcol * 8);
    float4 b1 = *reinterpret_cast<const float4*>(bias + tcol * 8 + 4);
    float bv[8] = {b0.x, b0.y, b0.z, b0.w, b1.x, b1.y, b1.z, b1.w};

    if (MODE == 0) {
#pragma unroll
        for (int i = 0; i < 8; i++) {
            int grow = row0 + trow * 8 + i;
            if (grow < N) {
                float o[8];
#pragma unroll
                for (int j = 0; j < 8; j++) o[j] = lrelu(acc[i][j] + bv[j]);
                float* dst = g_t + (size_t)grow * HDIM + tcol * 8;
                *reinterpret_cast<float4*>(dst)     = make_float4(o[0], o[1], o[2], o[3]);
                *reinterpret_cast<float4*>(dst + 4) = make_float4(o[4], o[5], o[6], o[7]);
            }
        }
    } else {
        float s0[8], s1[8];
#pragma unroll
        for (int j = 0; j < 8; j++) { s0[j] = 0.f; s1[j] = 0.f; }
        int curg = -1;
        float p[8];
#pragma unroll
        for (int j = 0; j < 8; j++) p[j] = 0.f;

#pragma unroll
        for (int i = 0; i < 8; i++) {
            int grow = row0 + trow * 8 + i;
            if (grow < N) {
                float o[8];
#pragma unroll
                for (int j = 0; j < 8; j++) {
                    o[j] = lrelu(acc[i][j] + bv[j]);
                    s0[j] += o[j];
                    s1[j] += o[j] * o[j];
                }
                if (!POOL) {
                    float* dst = g_h + (size_t)grow * HDIM + tcol * 8;
                    *reinterpret_cast<float4*>(dst)     = make_float4(o[0], o[1], o[2], o[3]);
                    *reinterpret_cast<float4*>(dst + 4) = make_float4(o[4], o[5], o[6], o[7]);
                } else {
                    int g = batch[grow];
                    if (g != curg) {
                        if (curg >= 0) {
                            float* dp = g_hg + (size_t)curg * HDIM + tcol * 8;
                            asm volatile("red.global.add.v4.f32 [%0], {%1, %2, %3, %4};"
                                         :: "l"(dp), "f"(p[0]), "f"(p[1]), "f"(p[2]), "f"(p[3]) : "memory");
                            asm volatile("red.global.add.v4.f32 [%0], {%1, %2, %3, %4};"
                                         :: "l"(dp + 4), "f"(p[4]), "f"(p[5]), "f"(p[6]), "f"(p[7]) : "memory");
                        }
                        curg = g;
#pragma unroll
                        for (int j = 0; j < 8; j++) p[j] = o[j];
                    } else {
#pragma unroll
                        for (int j = 0; j < 8; j++) p[j] += o[j];
                    }
                }
            }
        }
        if (POOL && curg >= 0) {
            float* dp = g_hg + (size_t)curg * HDIM + tcol * 8;
            asm volatile("red.global.add.v4.f32 [%0], {%1, %2, %3, %4};"
                         :: "l"(dp), "f"(p[0]), "f"(p[1]), "f"(p[2]), "f"(p[3]) : "memory");
            asm volatile("red.global.add.v4.f32 [%0], {%1, %2, %3, %4};"
                         :: "l"(dp + 4), "f"(p[4]), "f"(p[5]), "f"(p[6]), "f"(p[7]) : "memory");
        }

        // BN statistics: smem reduce then global double atomics
        csum[tid] = 0.f; csq[tid] = 0.f;
        __syncthreads();
#pragma unroll
        for (int j = 0; j < 8; j++) {
            atomicAdd(&csum[tcol * 8 + j], s0[j]);
            atomicAdd(&csq [tcol * 8 + j], s1[j]);
        }
        __syncthreads();
        atomicAdd(&g_stats[tid],        (double)csum[tid]);
        atomicAdd(&g_stats[HDIM + tid], (double)csq[tid]);
    }
}

// ---------------- BN coefficients (self-zeroes stats for next layer) ----------------
__global__ void coef_kernel(const float* __restrict__ gamma,
                            const float* __restrict__ beta, int N) {
    int c = threadIdx.x;
    double mean = g_stats[c] / (double)N;
    double var  = g_stats[HDIM + c] / (double)N - mean * mean;
    float a = (float)((double)gamma[c] / sqrt(var + (double)BN_EPS));
    g_coef[c]        = a;
    g_coef[HDIM + c] = beta[c] - a * (float)mean;
    g_stats[c] = 0.0;
    g_stats[HDIM + c] = 0.0;
}

// ---------------- head: hg = a2*raw + c2*cnt, MLP + log_softmax ----------------
__global__ void head_kernel(const float* __restrict__ fcW1, const float* __restrict__ fcb1,
                            const float* __restrict__ fcW2, const float* __restrict__ fcb2,
                            float* __restrict__ out) {
    __shared__ float s[HDIM];
    __shared__ float y[HDIM];
    __shared__ float z[NCLS];
    __shared__ float red2[2];
    int g = blockIdx.x;
    int j = threadIdx.x;

    float cnt = g_cnt[g];
    s[j] = g_coef[j] * g_hg[g * HDIM + j] + g_coef[HDIM + j] * cnt;
    __syncthreads();

    float acc = fcb1[j];
#pragma unroll 8
    for (int k = 0; k < HDIM; k++) acc += s[k] * fcW1[k * HDIM + j];
    y[j] = lrelu(acc);
    __syncthreads();

    if (j < NCLS) {
        float acc2 = fcb2[j];
#pragma unroll 8
        for (int k = 0; k < HDIM; k++) acc2 += y[k] * fcW2[k * NCLS + j];
        z[j] = acc2;
    }
    __syncthreads();

    if (j == 0) {
        float m = z[0];
#pragma unroll
        for (int c = 1; c < NCLS; c++) m = fmaxf(m, z[c]);
        float se = 0.f;
#pragma unroll
        for (int c = 0; c < NCLS; c++) se += expf(z[c] - m);
        red2[0] = m;
        red2[1] = logf(se);
    }
    __syncthreads();
    if (j < NCLS) out[g * NCLS + j] = z[j] - red2[0] - red2[1];
}

// ---------------- launch ----------------
extern "C" void kernel_launch(void* const* d_in, const int* in_sizes, int n_in,
                              void* d_out, int out_size) {
    const float* x    = (const float*)d_in[0];
    const float* W1a  = (const float*)d_in[1];
    const float* b1a  = (const float*)d_in[2];
    const float* W1b  = (const float*)d_in[3];
    const float* b1b  = (const float*)d_in[4];
    const float* g1   = (const float*)d_in[5];
    const float* be1  = (const float*)d_in[6];
    const float* W2a  = (const float*)d_in[7];
    const float* b2a  = (const float*)d_in[8];
    const float* W2b  = (const float*)d_in[9];
    const float* b2b  = (const float*)d_in[10];
    const float* g2   = (const float*)d_in[11];
    const float* be2  = (const float*)d_in[12];
    const float* fcW1 = (const float*)d_in[13];
    const float* fcb1 = (const float*)d_in[14];
    const float* fcW2 = (const float*)d_in[15];
    const float* fcb2 = (const float*)d_in[16];
    const int* ei     = (const int*)d_in[17];   // int32 (JAX x64 disabled)
    const int* batch  = (const int*)d_in[18];   // int32
    float* out = (float*)d_out;

    const int N = in_sizes[0] / HDIM;
    const int E = in_sizes[17] / 2;
    const int* esrc = ei;
    const int* edst = ei + E;

    const int gemmBlocks = (N + 63) / 64;
    const int aggBlocks  = (N + 7) / 8;
    const int eBlocks    = (E + 255) / 256;
    const int scanBlocks = (N + SCAN_CHUNK - 1) / SCAN_CHUNK;

    // ---- CSR build (once, reused by both layers) ----
    zero_kernel<<<512, 256>>>(N);
    hist_kernel<<<eBlocks, 256>>>(edst, batch, E, N);
    scan1_kernel<<<scanBlocks, 256>>>(N);
    scan2_kernel<<<1, MAXBLK>>>(scanBlocks);
    scan3_kernel<<<(N + 256) / 256, 256>>>(N, scanBlocks);
    fill_kernel<<<eBlocks, 256>>>(esrc, edst, E);

    // ---- layer 1 ----
    aggregate_kernel<0><<<aggBlocks, 256>>>(x, N);
    gemm_kernel<0, 0><<<gemmBlocks, 128>>>(W1a, b1a, nullptr, N);
    gemm_kernel<1, 0><<<gemmBlocks, 128>>>(W1b, b1b, nullptr, N);
    coef_kernel<<<1, HDIM>>>(g1, be1, N);

    // ---- layer 2 (BN1 folded into aggregation) ----
    aggregate_kernel<1><<<aggBlocks, 256>>>(nullptr, N);
    gemm_kernel<0, 0><<<gemmBlocks, 128>>>(W2a, b2a, nullptr, N);
    gemm_kernel<1, 1><<<gemmBlocks, 128>>>(W2b, b2b, batch, N);
    coef_kernel<<<1, HDIM>>>(g2, be2, N);

    // ---- head ----
    head_kernel<<<GMAX, HDIM>>>(fcW1, fcb1, fcW2, fcb2, out);
}

// round 10
// speedup vs baseline: 1.2576x; 1.1251x over previous
#include <cuda_runtime.h>
#include <cstdint>

#define HDIM 128
#define NMAX 100032
#define EMAX 1600000
#define GMAX 1024
#define NCLS 10
#define BN_EPS 1e-5
#define SLOPE 0.01f
#define SCAN_CHUNK 2048
#define MAXBLK 64

// ---------------- device scratch (static, no allocation) ----------------
__device__ __align__(16) float  g_agg[(size_t)NMAX * HDIM];
__device__ __align__(16) float  g_t  [(size_t)NMAX * HDIM];
__device__ __align__(16) float  g_h  [(size_t)NMAX * HDIM];
__device__ __align__(16) float  g_hg [GMAX * HDIM];
__device__ __align__(16) float  g_cnt[GMAX];
__device__ __align__(16) double g_stats[2 * HDIM];
__device__ __align__(16) float  g_coef [2 * HDIM];
__device__ int g_deg   [NMAX];
__device__ int g_rowptr[NMAX + 1];
__device__ int g_cur   [NMAX];
__device__ int g_eidx  [EMAX];
__device__ int g_bsum  [MAXBLK];
__device__ int g_boff  [MAXBLK];

__device__ __forceinline__ float lrelu(float x) { return x > 0.f ? x : SLOPE * x; }

// ---------------- zero small scratch + CSR counters ----------------
__global__ void zero_kernel(int N) {
    int idx    = blockIdx.x * blockDim.x + threadIdx.x;
    int stride = gridDim.x * blockDim.x;
    float4 z = make_float4(0.f, 0.f, 0.f, 0.f);
    float4* h4 = reinterpret_cast<float4*>(g_hg);
    for (int i = idx; i < (GMAX * HDIM) >> 2; i += stride) h4[i] = z;
    for (int i = idx; i < N; i += stride) { g_deg[i] = 0; g_cur[i] = 0; }
    if (idx < GMAX) g_cnt[idx] = 0.f;
    if (idx < 2 * HDIM) g_stats[idx] = 0.0;
}

// ---------------- combined edge histogram + per-graph node counts ----------------
__global__ void hist_kernel(const int* __restrict__ dst,
                            const int* __restrict__ batch, int E, int N) {
    int e = blockIdx.x * blockDim.x + threadIdx.x;
    if (e < E) atomicAdd(&g_deg[dst[e]], 1);
    if (e < N) atomicAdd(&g_cnt[batch[e]], 1.0f);
}

// ---------------- CSR build: 3-phase multi-block exclusive scan ----------------
__global__ void scan1_kernel(int N) {
    __shared__ int ts[256];
    int b = blockIdx.x;
    int t = threadIdx.x;
    int base = b * SCAN_CHUNK + t * 8;
    int v[8];
    int s = 0;
#pragma unroll
    for (int i = 0; i < 8; i++) {
        int idx = base + i;
        v[i] = (idx < N) ? g_deg[idx] : 0;
        s += v[i];
    }
    ts[t] = s;
    __syncthreads();
#pragma unroll
    for (int off = 1; off < 256; off <<= 1) {
        int x = (t >= off) ? ts[t - off] : 0;
        __syncthreads();
        ts[t] += x;
        __syncthreads();
    }
    int run = ts[t] - s;
#pragma unroll
    for (int i = 0; i < 8; i++) {
        int idx = base + i;
        if (idx < N) g_rowptr[idx] = run;
        run += v[i];
    }
    if (t == 255) g_bsum[b] = ts[255];
}

__global__ void scan2_kernel(int nb) {
    __shared__ int ts[MAXBLK];
    int t = threadIdx.x;
    int v = (t < nb) ? g_bsum[t] : 0;
    ts[t] = v;
    __syncthreads();
#pragma unroll
    for (int off = 1; off < MAXBLK; off <<= 1) {
        int x = (t >= off) ? ts[t - off] : 0;
        __syncthreads();
        ts[t] += x;
        __syncthreads();
    }
    g_boff[t] = ts[t] - v;
}

__global__ void scan3_kernel(int N, int nb) {
    int i = blockIdx.x * blockDim.x + threadIdx.x;
    if (i < N) g_rowptr[i] += g_boff[i / SCAN_CHUNK];
    if (i == N) g_rowptr[N] = g_boff[nb - 1] + g_bsum[nb - 1];
}

__global__ void fill_kernel(const int* __restrict__ src,
                            const int* __restrict__ dst, int E) {
    int e = blockIdx.x * blockDim.x + threadIdx.x;
    if (e < E) {
        int d = dst[e];
        int pos = atomicAdd(&g_cur[d], 1);
        g_eidx[g_rowptr[d] + pos] = src[e];
    }
}

// ---------------- gather aggregation: agg[i] = BN?( x[i] + sum_{j->i} x[j] ) ----------------
template<int APPLY_BN>
__global__ void aggregate_kernel(const float* __restrict__ Xext, int N) {
    int i = (blockIdx.x * blockDim.x + threadIdx.x) >> 5;
    if (i >= N) return;
    int lane = threadIdx.x & 31;
    const float* X = APPLY_BN ? g_h : Xext;
    int base = g_rowptr[i];
    int end  = g_rowptr[i + 1];

    float4 acc = *reinterpret_cast<const float4*>(X + (size_t)i * HDIM + lane * 4);
    int e = base;
    for (; e + 4 <= end; e += 4) {
        int s0 = g_eidx[e], s1 = g_eidx[e + 1], s2 = g_eidx[e + 2], s3 = g_eidx[e + 3];
        float4 v0 = *reinterpret_cast<const float4*>(X + (size_t)s0 * HDIM + lane * 4);
        float4 v1 = *reinterpret_cast<const float4*>(X + (size_t)s1 * HDIM + lane * 4);
        float4 v2 = *reinterpret_cast<const float4*>(X + (size_t)s2 * HDIM + lane * 4);
        float4 v3 = *reinterpret_cast<const float4*>(X + (size_t)s3 * HDIM + lane * 4);
        acc.x += v0.x + v1.x + v2.x + v3.x;
        acc.y += v0.y + v1.y + v2.y + v3.y;
        acc.z += v0.z + v1.z + v2.z + v3.z;
        acc.w += v0.w + v1.w + v2.w + v3.w;
    }
    for (; e < end; e++) {
        int s = g_eidx[e];
        float4 v = *reinterpret_cast<const float4*>(X + (size_t)s * HDIM + lane * 4);
        acc.x += v.x; acc.y += v.y; acc.z += v.z; acc.w += v.w;
    }
    if (APPLY_BN) {
        float cnt = (float)(end - base + 1);
        float4 a = *reinterpret_cast<const float4*>(&g_coef[lane * 4]);
        float4 c = *reinterpret_cast<const float4*>(&g_coef[HDIM + lane * 4]);
        acc.x = fmaf(a.x, acc.x, cnt * c.x);
        acc.y = fmaf(a.y, acc.y, cnt * c.y);
        acc.z = fmaf(a.z, acc.z, cnt * c.z);
        acc.w = fmaf(a.w, acc.w, cnt * c.w);
    }
    *reinterpret_cast<float4*>(g_agg + (size_t)i * HDIM + lane * 4) = acc;
}

// ---------------- fused GEMM (R6 tiling + SW-pipelined staging) ----------------
// 256 threads, 64x128 tile, BK=16, per-thread 8x4.
// MODE 0: A = g_agg -> g_t. MODE 1: A = g_t -> g_h (or pooled raw sums if POOL) + BN stats.
template<int MODE, int POOL>
__global__ void __launch_bounds__(256)
gemm_kernel(const float* __restrict__ W,
            const float* __restrict__ bias,
            const int* __restrict__ batch,
            int N) {
    __shared__ __align__(16) float As[16][72];
    __shared__ __align__(16) float Ws[16 * HDIM];
    __shared__ float csum[HDIM];
    __shared__ float csq [HDIM];

    const int tid  = threadIdx.x;
    const int tcol = tid & 31;
    const int trow = tid >> 5;
    const int row0 = blockIdx.x * 64;

    const float* X = (MODE == 0) ? g_agg : g_t;

    float acc[8][4];
#pragma unroll
    for (int i = 0; i < 8; i++)
#pragma unroll
        for (int j = 0; j < 4; j++) acc[i][j] = 0.f;

    const int lr = tid >> 2;
    const int lk = (tid & 3) * 4;
    const int grow = row0 + lr;
    const bool rowOK = grow < N;

    // prefetch chunk 0 into registers
    float4 avP = make_float4(0.f, 0.f, 0.f, 0.f);
    float4 wvP0, wvP1;
    if (rowOK)
        avP = *reinterpret_cast<const float4*>(X + (size_t)grow * HDIM + lk);
    {
        const float4* wsrc = reinterpret_cast<const float4*>(W);
        wvP0 = wsrc[tid];
        wvP1 = wsrc[tid + 256];
    }

    for (int ci = 0; ci < 8; ci++) {
        // store staged registers to smem
        As[lk + 0][lr] = avP.x;
        As[lk + 1][lr] = avP.y;
        As[lk + 2][lr] = avP.z;
        As[lk + 3][lr] = avP.w;
        {
            float4* wdst = reinterpret_cast<float4*>(Ws);
            wdst[tid]       = wvP0;
            wdst[tid + 256] = wvP1;
        }
        __syncthreads();

        // prefetch next chunk (LDG latency hidden by the compute below)
        if (ci < 7) {
            int k0n = (ci + 1) * 16;
            if (rowOK)
                avP = *reinterpret_cast<const float4*>(X + (size_t)grow * HDIM + k0n + lk);
            const float4* wsrc = reinterpret_cast<const float4*>(W + k0n * HDIM);
            wvP0 = wsrc[tid];
            wvP1 = wsrc[tid + 256];
        }

#pragma unroll
        for (int kk = 0; kk < 16; kk++) {
            float4 w  = *reinterpret_cast<float4*>(&Ws[kk * HDIM + tcol * 4]);
            float4 a0 = *reinterpret_cast<float4*>(&As[kk][trow * 8]);
            float4 a1 = *reinterpret_cast<float4*>(&As[kk][trow * 8 + 4]);
            float a[8] = {a0.x, a0.y, a0.z, a0.w, a1.x, a1.y, a1.z, a1.w};
#pragma unroll
            for (int i = 0; i < 8; i++) {
                acc[i][0] = fmaf(a[i], w.x, acc[i][0]);
                acc[i][1] = fmaf(a[i], w.y, acc[i][1]);
                acc[i][2] = fmaf(a[i], w.z, acc[i][2]);
                acc[i][3] = fmaf(a[i], w.w, acc[i][3]);
            }
        }
        __syncthreads();
    }

    float4 bv = *reinterpret_cast<const float4*>(bias + tcol * 4);

    if (MODE == 0) {
#pragma unroll
        for (int i = 0; i < 8; i++) {
            int r = row0 + trow * 8 + i;
            if (r < N) {
                float4 o;
                o.x = lrelu(acc[i][0] + bv.x);
                o.y = lrelu(acc[i][1] + bv.y);
                o.z = lrelu(acc[i][2] + bv.z);
                o.w = lrelu(acc[i][3] + bv.w);
                *reinterpret_cast<float4*>(g_t + (size_t)r * HDIM + tcol * 4) = o;
            }
        }
    } else {
        float s0[4] = {0.f, 0.f, 0.f, 0.f};
        float s1[4] = {0.f, 0.f, 0.f, 0.f};
        int curg = -1;
        float p[4] = {0.f, 0.f, 0.f, 0.f};

#pragma unroll
        for (int i = 0; i < 8; i++) {
            int r = row0 + trow * 8 + i;
            if (r < N) {
                float4 o;
                o.x = lrelu(acc[i][0] + bv.x);
                o.y = lrelu(acc[i][1] + bv.y);
                o.z = lrelu(acc[i][2] + bv.z);
                o.w = lrelu(acc[i][3] + bv.w);
                s0[0] += o.x; s1[0] += o.x * o.x;
                s0[1] += o.y; s1[1] += o.y * o.y;
                s0[2] += o.z; s1[2] += o.z * o.z;
                s0[3] += o.w; s1[3] += o.w * o.w;
                if (!POOL) {
                    *reinterpret_cast<float4*>(g_h + (size_t)r * HDIM + tcol * 4) = o;
                } else {
                    int g = batch[r];
                    if (g != curg) {
                        if (curg >= 0) {
                            float* dp = g_hg + (size_t)curg * HDIM + tcol * 4;
                            asm volatile("red.global.add.v4.f32 [%0], {%1, %2, %3, %4};"
                                         :: "l"(dp), "f"(p[0]), "f"(p[1]), "f"(p[2]), "f"(p[3]) : "memory");
                        }
                        curg = g;
                        p[0] = o.x; p[1] = o.y; p[2] = o.z; p[3] = o.w;
                    } else {
                        p[0] += o.x; p[1] += o.y; p[2] += o.z; p[3] += o.w;
                    }
                }
            }
        }
        if (POOL && curg >= 0) {
            float* dp = g_hg + (size_t)curg * HDIM + tcol * 4;
            asm volatile("red.global.add.v4.f32 [%0], {%1, %2, %3, %4};"
                         :: "l"(dp), "f"(p[0]), "f"(p[1]), "f"(p[2]), "f"(p[3]) : "memory");
        }

        if (tid < HDIM) { csum[tid] = 0.f; csq[tid] = 0.f; }
        __syncthreads();
#pragma unroll
        for (int j = 0; j < 4; j++) {
            atomicAdd(&csum[tcol * 4 + j], s0[j]);
            atomicAdd(&csq [tcol * 4 + j], s1[j]);
        }
        __syncthreads();
        if (tid < HDIM) {
            atomicAdd(&g_stats[tid],        (double)csum[tid]);
            atomicAdd(&g_stats[HDIM + tid], (double)csq[tid]);
        }
    }
}

// ---------------- BN coefficients (self-zeroes stats for next layer) ----------------
__global__ void coef_kernel(const float* __restrict__ gamma,
                            const float* __restrict__ beta, int N) {
    int c = threadIdx.x;
    double mean = g_stats[c] / (double)N;
    double var  = g_stats[HDIM + c] / (double)N - mean * mean;
    float a = (float)((double)gamma[c] / sqrt(var + (double)BN_EPS));
    g_coef[c]        = a;
    g_coef[HDIM + c] = beta[c] - a * (float)mean;
    g_stats[c] = 0.0;
    g_stats[HDIM + c] = 0.0;
}

// ---------------- head: hg = a2*raw + c2*cnt, MLP + log_softmax ----------------
__global__ void head_kernel(const float* __restrict__ fcW1, const float* __restrict__ fcb1,
                            const float* __restrict__ fcW2, const float* __restrict__ fcb2,
                            float* __restrict__ out) {
    __shared__ float s[HDIM];
    __shared__ float y[HDIM];
    __shared__ float z[NCLS];
    __shared__ float red2[2];
    int g = blockIdx.x;
    int j = threadIdx.x;

    float cnt = g_cnt[g];
    s[j] = g_coef[j] * g_hg[g * HDIM + j] + g_coef[HDIM + j] * cnt;
    __syncthreads();

    float acc = fcb1[j];
#pragma unroll 8
    for (int k = 0; k < HDIM; k++) acc += s[k] * fcW1[k * HDIM + j];
    y[j] = lrelu(acc);
    __syncthreads();

    if (j < NCLS) {
        float acc2 = fcb2[j];
#pragma unroll 8
        for (int k = 0; k < HDIM; k++) acc2 += y[k] * fcW2[k * NCLS + j];
        z[j] = acc2;
    }
    __syncthreads();

    if (j == 0) {
        float m = z[0];
#pragma unroll
        for (int c = 1; c < NCLS; c++) m = fmaxf(m, z[c]);
        float se = 0.f;
#pragma unroll
        for (int c = 0; c < NCLS; c++) se += expf(z[c] - m);
        red2[0] = m;
        red2[1] = logf(se);
    }
    __syncthreads();
    if (j < NCLS) out[g * NCLS + j] = z[j] - red2[0] - red2[1];
}

// ---------------- launch ----------------
extern "C" void kernel_launch(void* const* d_in, const int* in_sizes, int n_in,
                              void* d_out, int out_size) {
    const float* x    = (const float*)d_in[0];
    const float* W1a  = (const float*)d_in[1];
    const float* b1a  = (const float*)d_in[2];
    const float* W1b  = (const float*)d_in[3];
    const float* b1b  = (const float*)d_in[4];
    const float* g1   = (const float*)d_in[5];
    const float* be1  = (const float*)d_in[6];
    const float* W2a  = (const float*)d_in[7];
    const float* b2a  = (const float*)d_in[8];
    const float* W2b  = (const float*)d_in[9];
    const float* b2b  = (const float*)d_in[10];
    const float* g2   = (const float*)d_in[11];
    const float* be2  = (const float*)d_in[12];
    const float* fcW1 = (const float*)d_in[13];
    const float* fcb1 = (const float*)d_in[14];
    const float* fcW2 = (const float*)d_in[15];
    const float* fcb2 = (const float*)d_in[16];
    const int* ei     = (const int*)d_in[17];   // int32 (JAX x64 disabled)
    const int* batch  = (const int*)d_in[18];   // int32
    float* out = (float*)d_out;

    const int N = in_sizes[0] / HDIM;
    const int E = in_sizes[17] / 2;
    const int* esrc = ei;
    const int* edst = ei + E;

    const int gemmBlocks = (N + 63) / 64;
    const int aggBlocks  = (N + 7) / 8;
    const int eBlocks    = (E + 255) / 256;
    const int scanBlocks = (N + SCAN_CHUNK - 1) / SCAN_CHUNK;

    // ---- CSR build (once, reused by both layers) ----
    zero_kernel<<<512, 256>>>(N);
    hist_kernel<<<eBlocks, 256>>>(edst, batch, E, N);
    scan1_kernel<<<scanBlocks, 256>>>(N);
    scan2_kernel<<<1, MAXBLK>>>(scanBlocks);
    scan3_kernel<<<(N + 256) / 256, 256>>>(N, scanBlocks);
    fill_kernel<<<eBlocks, 256>>>(esrc, edst, E);

    // ---- layer 1 ----
    aggregate_kernel<0><<<aggBlocks, 256>>>(x, N);
    gemm_kernel<0, 0><<<gemmBlocks, 256>>>(W1a, b1a, nullptr, N);
    gemm_kernel<1, 0><<<gemmBlocks, 256>>>(W1b, b1b, nullptr, N);
    coef_kernel<<<1, HDIM>>>(g1, be1, N);

    // ---- layer 2 (BN1 folded into aggregation) ----
    aggregate_kernel<1><<<aggBlocks, 256>>>(nullptr, N);
    gemm_kernel<0, 0><<<gemmBlocks, 256>>>(W2a, b2a, nullptr, N);
    gemm_kernel<1, 1><<<gemmBlocks, 256>>>(W2b, b2b, batch, N);
    coef_kernel<<<1, HDIM>>>(g2, be2, N);

    // ---- head ----
    head_kernel<<<GMAX, HDIM>>>(fcW1, fcb1, fcW2, fcb2, out);
}

// round 11
// speedup vs baseline: 1.2960x; 1.0306x over previous
#include <cuda_runtime.h>
#include <cstdint>

#define HDIM 128
#define NMAX 100032
#define EMAX 1600000
#define GMAX 1024
#define NCLS 10
#define BN_EPS 1e-5
#define SLOPE 0.01f
#define SCAN_CHUNK 2048
#define MAXBLK 64

// ---------------- device scratch (static, no allocation) ----------------
__device__ __align__(16) float  g_agg[(size_t)NMAX * HDIM];
__device__ __align__(16) float  g_h  [(size_t)NMAX * HDIM];
__device__ __align__(16) float  g_hg [GMAX * HDIM];
__device__ __align__(16) float  g_cnt[GMAX];
__device__ __align__(16) double g_stats[2 * HDIM];
__device__ __align__(16) float  g_coef [2 * HDIM];
__device__ int g_deg   [NMAX];
__device__ int g_rowptr[NMAX + 1];
__device__ int g_cur   [NMAX];
__device__ int g_eidx  [EMAX];
__device__ int g_bsum  [MAXBLK];
__device__ int g_boff  [MAXBLK];

__device__ __forceinline__ float lrelu(float x) { return x > 0.f ? x : SLOPE * x; }

// ---------------- zero small scratch + CSR counters ----------------
__global__ void zero_kernel(int N) {
    int idx    = blockIdx.x * blockDim.x + threadIdx.x;
    int stride = gridDim.x * blockDim.x;
    float4 z = make_float4(0.f, 0.f, 0.f, 0.f);
    float4* h4 = reinterpret_cast<float4*>(g_hg);
    for (int i = idx; i < (GMAX * HDIM) >> 2; i += stride) h4[i] = z;
    for (int i = idx; i < N; i += stride) g_deg[i] = 0;
    if (idx < GMAX) g_cnt[idx] = 0.f;
    if (idx < 2 * HDIM) g_stats[idx] = 0.0;
}

// ---------------- combined edge histogram + per-graph node counts ----------------
__global__ void hist_kernel(const int* __restrict__ dst,
                            const int* __restrict__ batch, int E, int N) {
    int e = blockIdx.x * blockDim.x + threadIdx.x;
    if (e < E) atomicAdd(&g_deg[dst[e]], 1);
    if (e < N) atomicAdd(&g_cnt[batch[e]], 1.0f);
}

// ---------------- CSR build: 3-phase multi-block exclusive scan ----------------
__global__ void scan1_kernel(int N) {
    __shared__ int ts[256];
    int b = blockIdx.x;
    int t = threadIdx.x;
    int base = b * SCAN_CHUNK + t * 8;
    int v[8];
    int s = 0;
#pragma unroll
    for (int i = 0; i < 8; i++) {
        int idx = base + i;
        v[i] = (idx < N) ? g_deg[idx] : 0;
        s += v[i];
    }
    ts[t] = s;
    __syncthreads();
#pragma unroll
    for (int off = 1; off < 256; off <<= 1) {
        int x = (t >= off) ? ts[t - off] : 0;
        __syncthreads();
        ts[t] += x;
        __syncthreads();
    }
    int run = ts[t] - s;
#pragma unroll
    for (int i = 0; i < 8; i++) {
        int idx = base + i;
        if (idx < N) g_rowptr[idx] = run;
        run += v[i];
    }
    if (t == 255) g_bsum[b] = ts[255];
}

__global__ void scan2_kernel(int nb) {
    __shared__ int ts[MAXBLK];
    int t = threadIdx.x;
    int v = (t < nb) ? g_bsum[t] : 0;
    ts[t] = v;
    __syncthreads();
#pragma unroll
    for (int off = 1; off < MAXBLK; off <<= 1) {
        int x = (t >= off) ? ts[t - off] : 0;
        __syncthreads();
        ts[t] += x;
        __syncthreads();
    }
    g_boff[t] = ts[t] - v;
}

// phase 3: add block offsets; also init fill cursor to absolute rowptr
__global__ void scan3_kernel(int N, int nb) {
    int i = blockIdx.x * blockDim.x + threadIdx.x;
    if (i < N) {
        int rp = g_rowptr[i] + g_boff[i / SCAN_CHUNK];
        g_rowptr[i] = rp;
        g_cur[i]    = rp;
    }
    if (i == N) g_rowptr[N] = g_boff[nb - 1] + g_bsum[nb - 1];
}

__global__ void fill_kernel(const int* __restrict__ src,
                            const int* __restrict__ dst, int E) {
    int e = blockIdx.x * blockDim.x + threadIdx.x;
    if (e < E) {
        int pos = atomicAdd(&g_cur[dst[e]], 1);   // absolute cursor
        g_eidx[pos] = src[e];
    }
}

// ---------------- gather aggregation: agg[i] = BN?( x[i] + sum_{j->i} x[j] ) ----------------
template<int APPLY_BN>
__global__ void aggregate_kernel(const float* __restrict__ Xext, int N) {
    int i = (blockIdx.x * blockDim.x + threadIdx.x) >> 5;
    if (i >= N) return;
    int lane = threadIdx.x & 31;
    const float* X = APPLY_BN ? g_h : Xext;
    int base = g_rowptr[i];
    int end  = g_rowptr[i + 1];

    float4 acc = *reinterpret_cast<const float4*>(X + (size_t)i * HDIM + lane * 4);
    int e = base;
    for (; e + 4 <= end; e += 4) {
        int s0 = g_eidx[e], s1 = g_eidx[e + 1], s2 = g_eidx[e + 2], s3 = g_eidx[e + 3];
        float4 v0 = *reinterpret_cast<const float4*>(X + (size_t)s0 * HDIM + lane * 4);
        float4 v1 = *reinterpret_cast<const float4*>(X + (size_t)s1 * HDIM + lane * 4);
        float4 v2 = *reinterpret_cast<const float4*>(X + (size_t)s2 * HDIM + lane * 4);
        float4 v3 = *reinterpret_cast<const float4*>(X + (size_t)s3 * HDIM + lane * 4);
        acc.x += v0.x + v1.x + v2.x + v3.x;
        acc.y += v0.y + v1.y + v2.y + v3.y;
        acc.z += v0.z + v1.z + v2.z + v3.z;
        acc.w += v0.w + v1.w + v2.w + v3.w;
    }
    for (; e < end; e++) {
        int s = g_eidx[e];
        float4 v = *reinterpret_cast<const float4*>(X + (size_t)s * HDIM + lane * 4);
        acc.x += v.x; acc.y += v.y; acc.z += v.z; acc.w += v.w;
    }
    if (APPLY_BN) {
        float cnt = (float)(end - base + 1);
        float4 a = *reinterpret_cast<const float4*>(&g_coef[lane * 4]);
        float4 c = *reinterpret_cast<const float4*>(&g_coef[HDIM + lane * 4]);
        acc.x = fmaf(a.x, acc.x, cnt * c.x);
        acc.y = fmaf(a.y, acc.y, cnt * c.y);
        acc.z = fmaf(a.z, acc.z, cnt * c.z);
        acc.w = fmaf(a.w, acc.w, cnt * c.w);
    }
    *reinterpret_cast<float4*>(g_agg + (size_t)i * HDIM + lane * 4) = acc;
}

// ---------------- fused GIN layer: h = leaky(A@Wa+ba) @ Wb + bb (+leaky/stats/pool) ----------
// 256 threads, 64-row tile, per-thread 8x4. Phase 1: A=g_agg -> U (smem).
// Phase 2: U @ Wb. POOL=0: out g_h + BN stats. POOL=1: pooled raw graph sums + BN stats.
template<int POOL>
__global__ void __launch_bounds__(256)
gin_layer(const float* __restrict__ Wa, const float* __restrict__ ba,
          const float* __restrict__ Wb, const float* __restrict__ bb,
          const int* __restrict__ batch, int N) {
    __shared__ __align__(16) float As[16][72];
    __shared__ __align__(16) float Ws[16 * HDIM];
    __shared__ __align__(16) float U [64 * HDIM];
    __shared__ float csum[HDIM];
    __shared__ float csq [HDIM];

    const int tid  = threadIdx.x;
    const int tcol = tid & 31;
    const int trow = tid >> 5;
    const int row0 = blockIdx.x * 64;

    float acc[8][4];
#pragma unroll
    for (int i = 0; i < 8; i++)
#pragma unroll
        for (int j = 0; j < 4; j++) acc[i][j] = 0.f;

    const int lr = tid >> 2;
    const int lk = (tid & 3) * 4;
    const int grow = row0 + lr;
    const bool rowOK = grow < N;

    // ---------------- phase 1: U = leaky(A @ Wa + ba) ----------------
    float4 avP = make_float4(0.f, 0.f, 0.f, 0.f);
    float4 wvP0, wvP1;
    if (rowOK)
        avP = *reinterpret_cast<const float4*>(g_agg + (size_t)grow * HDIM + lk);
    {
        const float4* wsrc = reinterpret_cast<const float4*>(Wa);
        wvP0 = wsrc[tid];
        wvP1 = wsrc[tid + 256];
    }

    for (int ci = 0; ci < 8; ci++) {
        As[lk + 0][lr] = avP.x;
        As[lk + 1][lr] = avP.y;
        As[lk + 2][lr] = avP.z;
        As[lk + 3][lr] = avP.w;
        {
            float4* wdst = reinterpret_cast<float4*>(Ws);
            wdst[tid]       = wvP0;
            wdst[tid + 256] = wvP1;
        }
        __syncthreads();

        if (ci < 7) {
            int k0n = (ci + 1) * 16;
            if (rowOK)
                avP = *reinterpret_cast<const float4*>(g_agg + (size_t)grow * HDIM + k0n + lk);
            const float4* wsrc = reinterpret_cast<const float4*>(Wa + k0n * HDIM);
            wvP0 = wsrc[tid];
            wvP1 = wsrc[tid + 256];
        } else {
            // prefetch Wb chunk 0 for phase 2
            const float4* wsrc = reinterpret_cast<const float4*>(Wb);
            wvP0 = wsrc[tid];
            wvP1 = wsrc[tid + 256];
        }

#pragma unroll
        for (int kk = 0; kk < 16; kk++) {
            float4 w  = *reinterpret_cast<float4*>(&Ws[kk * HDIM + tcol * 4]);
            float4 a0 = *reinterpret_cast<float4*>(&As[kk][trow * 8]);
            float4 a1 = *reinterpret_cast<float4*>(&As[kk][trow * 8 + 4]);
            float a[8] = {a0.x, a0.y, a0.z, a0.w, a1.x, a1.y, a1.z, a1.w};
#pragma unroll
            for (int i = 0; i < 8; i++) {
                acc[i][0] = fmaf(a[i], w.x, acc[i][0]);
                acc[i][1] = fmaf(a[i], w.y, acc[i][1]);
                acc[i][2] = fmaf(a[i], w.z, acc[i][2]);
                acc[i][3] = fmaf(a[i], w.w, acc[i][3]);
            }
        }
        __syncthreads();
    }

    // phase-1 epilogue: U[row][col] = leaky(acc + ba); per-warp rows -> contiguous stores
    {
        float4 bv = *reinterpret_cast<const float4*>(ba + tcol * 4);
#pragma unroll
        for (int i = 0; i < 8; i++) {
            float4 o;
            o.x = lrelu(acc[i][0] + bv.x);
            o.y = lrelu(acc[i][1] + bv.y);
            o.z = lrelu(acc[i][2] + bv.z);
            o.w = lrelu(acc[i][3] + bv.w);
            *reinterpret_cast<float4*>(&U[(trow * 8 + i) * HDIM + tcol * 4]) = o;
        }
    }
#pragma unroll
    for (int i = 0; i < 8; i++)
#pragma unroll
        for (int j = 0; j < 4; j++) acc[i][j] = 0.f;
    __syncthreads();

    // ---------------- phase 2: out = U @ Wb ----------------
    for (int ci = 0; ci < 8; ci++) {
        {
            float4* wdst = reinterpret_cast<float4*>(Ws);
            wdst[tid]       = wvP0;
            wdst[tid + 256] = wvP1;
        }
        __syncthreads();

        if (ci < 7) {
            int k0n = (ci + 1) * 16;
            const float4* wsrc = reinterpret_cast<const float4*>(Wb + k0n * HDIM);
            wvP0 = wsrc[tid];
            wvP1 = wsrc[tid + 256];
        }

        const int k0 = ci * 16;
#pragma unroll
        for (int kq = 0; kq < 4; kq++) {
            // 4 weight vectors for k = k0+kq*4 .. +3  (col slice tcol*4..+3)
            float4 w0 = *reinterpret_cast<float4*>(&Ws[(kq * 4 + 0) * HDIM + tcol * 4]);
            float4 w1 = *reinterpret_cast<float4*>(&Ws[(kq * 4 + 1) * HDIM + tcol * 4]);
            float4 w2 = *reinterpret_cast<float4*>(&Ws[(kq * 4 + 2) * HDIM + tcol * 4]);
            float4 w3 = *reinterpret_cast<float4*>(&Ws[(kq * 4 + 3) * HDIM + tcol * 4]);
#pragma unroll
            for (int i = 0; i < 8; i++) {
                // broadcast read: all lanes in warp read the same U row slice
                float4 a = *reinterpret_cast<float4*>(&U[(trow * 8 + i) * HDIM + k0 + kq * 4]);
                acc[i][0] = fmaf(a.x, w0.x, acc[i][0]);
                acc[i][1] = fmaf(a.x, w0.y, acc[i][1]);
                acc[i][2] = fmaf(a.x, w0.z, acc[i][2]);
                acc[i][3] = fmaf(a.x, w0.w, acc[i][3]);
                acc[i][0] = fmaf(a.y, w1.x, acc[i][0]);
                acc[i][1] = fmaf(a.y, w1.y, acc[i][1]);
                acc[i][2] = fmaf(a.y, w1.z, acc[i][2]);
                acc[i][3] = fmaf(a.y, w1.w, acc[i][3]);
                acc[i][0] = fmaf(a.z, w2.x, acc[i][0]);
                acc[i][1] = fmaf(a.z, w2.y, acc[i][1]);
                acc[i][2] = fmaf(a.z, w2.z, acc[i][2]);
                acc[i][3] = fmaf(a.z, w2.w, acc[i][3]);
                acc[i][0] = fmaf(a.w, w3.x, acc[i][0]);
                acc[i][1] = fmaf(a.w, w3.y, acc[i][1]);
                acc[i][2] = fmaf(a.w, w3.z, acc[i][2]);
                acc[i][3] = fmaf(a.w, w3.w, acc[i][3]);
            }
        }
        __syncthreads();
    }

    // ---------------- phase-2 epilogue ----------------
    float4 bv = *reinterpret_cast<const float4*>(bb + tcol * 4);
    float s0[4] = {0.f, 0.f, 0.f, 0.f};
    float s1[4] = {0.f, 0.f, 0.f, 0.f};
    int curg = -1;
    float p[4] = {0.f, 0.f, 0.f, 0.f};

#pragma unroll
    for (int i = 0; i < 8; i++) {
        int r = row0 + trow * 8 + i;
        if (r < N) {
            float4 o;
            o.x = lrelu(acc[i][0] + bv.x);
            o.y = lrelu(acc[i][1] + bv.y);
            o.z = lrelu(acc[i][2] + bv.z);
            o.w = lrelu(acc[i][3] + bv.w);
            s0[0] += o.x; s1[0] += o.x * o.x;
            s0[1] += o.y; s1[1] += o.y * o.y;
            s0[2] += o.z; s1[2] += o.z * o.z;
            s0[3] += o.w; s1[3] += o.w * o.w;
            if (!POOL) {
                *reinterpret_cast<float4*>(g_h + (size_t)r * HDIM + tcol * 4) = o;
            } else {
                int g = batch[r];
                if (g != curg) {
                    if (curg >= 0) {
                        float* dp = g_hg + (size_t)curg * HDIM + tcol * 4;
                        asm volatile("red.global.add.v4.f32 [%0], {%1, %2, %3, %4};"
                                     :: "l"(dp), "f"(p[0]), "f"(p[1]), "f"(p[2]), "f"(p[3]) : "memory");
                    }
                    curg = g;
                    p[0] = o.x; p[1] = o.y; p[2] = o.z; p[3] = o.w;
                } else {
                    p[0] += o.x; p[1] += o.y; p[2] += o.z; p[3] += o.w;
                }
            }
        }
    }
    if (POOL && curg >= 0) {
        float* dp = g_hg + (size_t)curg * HDIM + tcol * 4;
        asm volatile("red.global.add.v4.f32 [%0], {%1, %2, %3, %4};"
                     :: "l"(dp), "f"(p[0]), "f"(p[1]), "f"(p[2]), "f"(p[3]) : "memory");
    }

    if (tid < HDIM) { csum[tid] = 0.f; csq[tid] = 0.f; }
    __syncthreads();
#pragma unroll
    for (int j = 0; j < 4; j++) {
        atomicAdd(&csum[tcol * 4 + j], s0[j]);
        atomicAdd(&csq [tcol * 4 + j], s1[j]);
    }
    __syncthreads();
    if (tid < HDIM) {
        atomicAdd(&g_stats[tid],        (double)csum[tid]);
        atomicAdd(&g_stats[HDIM + tid], (double)csq[tid]);
    }
}

// ---------------- BN coefficients (self-zeroes stats for next layer) ----------------
__global__ void coef_kernel(const float* __restrict__ gamma,
                            const float* __restrict__ beta, int N) {
    int c = threadIdx.x;
    double mean = g_stats[c] / (double)N;
    double var  = g_stats[HDIM + c] / (double)N - mean * mean;
    float a = (float)((double)gamma[c] / sqrt(var + (double)BN_EPS));
    g_coef[c]        = a;
    g_coef[HDIM + c] = beta[c] - a * (float)mean;
    g_stats[c] = 0.0;
    g_stats[HDIM + c] = 0.0;
}

// ---------------- head: hg = a2*raw + c2*cnt, MLP + log_softmax ----------------
__global__ void head_kernel(const float* __restrict__ fcW1, const float* __restrict__ fcb1,
                            const float* __restrict__ fcW2, const float* __restrict__ fcb2,
                            float* __restrict__ out) {
    __shared__ float s[HDIM];
    __shared__ float y[HDIM];
    __shared__ float z[NCLS];
    __shared__ float red2[2];
    int g = blockIdx.x;
    int j = threadIdx.x;

    float cnt = g_cnt[g];
    s[j] = g_coef[j] * g_hg[g * HDIM + j] + g_coef[HDIM + j] * cnt;
    __syncthreads();

    float acc = fcb1[j];
#pragma unroll 8
    for (int k = 0; k < HDIM; k++) acc += s[k] * fcW1[k * HDIM + j];
    y[j] = lrelu(acc);
    __syncthreads();

    if (j < NCLS) {
        float acc2 = fcb2[j];
#pragma unroll 8
        for (int k = 0; k < HDIM; k++) acc2 += y[k] * fcW2[k * NCLS + j];
        z[j] = acc2;
    }
    __syncthreads();

    if (j == 0) {
        float m = z[0];
#pragma unroll
        for (int c = 1; c < NCLS; c++) m = fmaxf(m, z[c]);
        float se = 0.f;
#pragma unroll
        for (int c = 0; c < NCLS; c++) se += expf(z[c] - m);
        red2[0] = m;
        red2[1] = logf(se);
    }
    __syncthreads();
    if (j < NCLS) out[g * NCLS + j] = z[j] - red2[0] - red2[1];
}

// ---------------- launch ----------------
extern "C" void kernel_launch(void* const* d_in, const int* in_sizes, int n_in,
                              void* d_out, int out_size) {
    const float* x    = (const float*)d_in[0];
    const float* W1a  = (const float*)d_in[1];
    const float* b1a  = (const float*)d_in[2];
    const float* W1b  = (const float*)d_in[3];
    const float* b1b  = (const float*)d_in[4];
    const float* g1   = (const float*)d_in[5];
    const float* be1  = (const float*)d_in[6];
    const float* W2a  = (const float*)d_in[7];
    const float* b2a  = (const float*)d_in[8];
    const float* W2b  = (const float*)d_in[9];
    const float* b2b  = (const float*)d_in[10];
    const float* g2   = (const float*)d_in[11];
    const float* be2  = (const float*)d_in[12];
    const float* fcW1 = (const float*)d_in[13];
    const float* fcb1 = (const float*)d_in[14];
    const float* fcW2 = (const float*)d_in[15];
    const float* fcb2 = (const float*)d_in[16];
    const int* ei     = (const int*)d_in[17];   // int32 (JAX x64 disabled)
    const int* batch  = (const int*)d_in[18];   // int32
    float* out = (float*)d_out;

    const int N = in_sizes[0] / HDIM;
    const int E = in_sizes[17] / 2;
    const int* esrc = ei;
    const int* edst = ei + E;

    const int gemmBlocks = (N + 63) / 64;
    const int aggBlocks  = (N + 7) / 8;
    const int eBlocks    = (E + 255) / 256;
    const int scanBlocks = (N + SCAN_CHUNK - 1) / SCAN_CHUNK;

    // ---- CSR build (once, reused by both layers) ----
    zero_kernel<<<512, 256>>>(N);
    hist_kernel<<<eBlocks, 256>>>(edst, batch, E, N);
    scan1_kernel<<<scanBlocks, 256>>>(N);
    scan2_kernel<<<1, MAXBLK>>>(scanBlocks);
    scan3_kernel<<<(N + 256) / 256, 256>>>(N, scanBlocks);
    fill_kernel<<<eBlocks, 256>>>(esrc, edst, E);

    // ---- layer 1 (fused double GEMM) ----
    aggregate_kernel<0><<<aggBlocks, 256>>>(x, N);
    gin_layer<0><<<gemmBlocks, 256>>>(W1a, b1a, W1b, b1b, nullptr, N);
    coef_kernel<<<1, HDIM>>>(g1, be1, N);

    // ---- layer 2 (BN1 folded into aggregation; pool fused into epilogue) ----
    aggregate_kernel<1><<<aggBlocks, 256>>>(nullptr, N);
    gin_layer<1><<<gemmBlocks, 256>>>(W2a, b2a, W2b, b2b, batch, N);
    coef_kernel<<<1, HDIM>>>(g2, be2, N);

    // ---- head ----
    head_kernel<<<GMAX, HDIM>>>(fcW1, fcb1, fcW2, fcb2, out);
}